// round 10
// baseline (speedup 1.0000x reference)
#include <cuda_runtime.h>
#include <cuda_bf16.h>
#include <cuda_fp16.h>
#include <math.h>
#include <stdint.h>

#define B_SZ  4
#define SEQ   4096
#define FEAT  1024
#define STATE 64
#define HIDN  4096
#define BS    (B_SZ*SEQ)      /* 16384 */
#define C6F   (6*FEAT)        /* 6144  */
#define KCAT  (256+FEAT)      /* 1280  */
#define LN_EPS 1e-5f

// ---------------- scratch (device globals; no allocation allowed) ----------------
__device__ float  g_bu[2*2*B_SZ*STATE*SEQ];           // [(d*2+p)][b][n][s] fp32
__device__ float  g_xmid[BS*FEAT];
__device__ float  g_ada[B_SZ*C6F];
__device__ float  g_silu[B_SZ*FEAT];
__device__ float  g_Wp[FEAT*256];                     // fp32 [K=1024][N=256]
__device__ float  g_Wcat[KCAT*FEAT];                  // fp32 [K=1280][N=1024]; rows 0:256=E, 256:1280=G
__device__ float  g_CtS[256*FEAT];
__device__ float2 g_Abar[2*STATE];
__device__ float2 g_coef[2*STATE];
// fp16 activation / weight buffers
__device__ __half g_acat[(size_t)BS*1280];     // [row][1280] = [xs(256)|h(1024)]
__device__ __half g_h2  [(size_t)BS*1024];     // [row][1024]
__device__ __half g_hid [(size_t)BS*4096];     // [row][4096]
__device__ __half g_wp2 [256*1024];            // [N=256][K=1024]
__device__ __half g_wcat2[(size_t)1024*1280];  // [N=1024][K=1280]
__device__ __half g_w12 [(size_t)4096*1024];   // [N=4096][K=1024]
__device__ __half g_w22 [(size_t)1024*4096];   // [N=1024][K=4096]

// ---------------- helpers ----------------
__device__ __forceinline__ uint32_t smem_u32(const void* p){
    uint32_t a; asm("{ .reg .u64 t; cvta.to.shared.u64 t, %1; cvt.u32.u64 %0, t; }":"=r"(a):"l"(p)); return a;
}
__device__ __forceinline__ void cp16(uint32_t dst, const void* src){
    asm volatile("cp.async.cg.shared.global [%0], [%1], 16;"::"r"(dst),"l"(src):"memory");
}
#define SW128(o) ((o) ^ (((o)>>3)&0x70))

// ---------------- small setup kernels ----------------
__global__ void k_coef(const float* fLA, const float* fAi, const float* fdt,
                       const float* bLA, const float* bAi, const float* bdt) {
    int t = threadIdx.x;
    if (t >= 128) return;
    int d = t >> 6, n = t & 63;
    const float* LA  = d ? bLA : fLA;
    const float* Ai  = d ? bAi : fAi;
    const float* LDT = d ? bdt : fdt;
    float dt = expf(LDT[n]);
    float ar = -expf(LA[n]);
    float ai = Ai[n];
    float e  = expf(ar*dt);
    float Abr = e*cosf(ai*dt);
    float Abi = e*sinf(ai*dt);
    float dr = ar + 1e-8f, di = ai;
    float den = dr*dr + di*di;
    float nr = Abr - 1.0f, ni = Abi;
    g_Abar[t] = make_float2(Abr, Abi);
    g_coef[t] = make_float2((nr*dr + ni*di)/den, (ni*dr - nr*di)/den);
}

__global__ void k_silu(const float* __restrict__ cond) {
    int i = blockIdx.x*256 + threadIdx.x;
    if (i < B_SZ*FEAT) { float c = cond[i]; g_silu[i] = c / (1.0f + expf(-c)); }
}

__global__ void k_ada(const float* __restrict__ W, const float* __restrict__ bias) {
    __shared__ float sc[B_SZ*FEAT];
    int tid = threadIdx.x;
    for (int i = tid; i < B_SZ*FEAT; i += 256) sc[i] = g_silu[i];
    __syncthreads();
    int col = blockIdx.x*256 + tid;
    float a0=0.f, a1=0.f, a2=0.f, a3=0.f;
    for (int k = 0; k < FEAT; k++) {
        float w = W[k*C6F + col];
        a0 += sc[k]*w; a1 += sc[FEAT+k]*w; a2 += sc[2*FEAT+k]*w; a3 += sc[3*FEAT+k]*w;
    }
    float bb = bias[col];
    g_ada[col]       = a0 + bb;
    g_ada[C6F+col]   = a1 + bb;
    g_ada[2*C6F+col] = a2 + bb;
    g_ada[3*C6F+col] = a3 + bb;
}

__global__ void k_wp(const float* fBr, const float* fBi, const float* bBr, const float* bBi) {
    int idx = blockIdx.x*256 + threadIdx.x;   // FEAT*256
    int c = idx & 255, f = idx >> 8;
    int d = c >> 7, p = (c >> 6) & 1, n = c & 63;
    float2 co = g_coef[d*64 + n];
    const float* Br = d ? bBr : fBr;
    const float* Bi = d ? bBi : fBi;
    float br = Br[n*FEAT + f], bi = Bi[n*FEAT + f];
    g_Wp[idx] = p ? (co.x*bi + co.y*br) : (co.x*br - co.y*bi);
}

__global__ void k_cts(const float* fCr, const float* fCi, const float* bCr, const float* bCi) {
    int idx = blockIdx.x*256 + threadIdx.x;   // 256*FEAT
    int f = idx & (FEAT-1), c = idx >> 10;
    int d = c >> 7, p = (c >> 6) & 1, n = c & 63;
    const float* Cp = p ? (d ? bCi : fCi) : (d ? bCr : fCr);
    float v = Cp[f*STATE + n];
    g_CtS[idx] = p ? -v : v;
}

__global__ void k_G(const float* fD, const float* bD, const float* oW) {
    int idx = blockIdx.x*256 + threadIdx.x;   // FEAT*FEAT
    int fp = idx & (FEAT-1), f = idx >> 10;
    g_Wcat[(256+f)*FEAT + fp] = fD[f]*oW[f*FEAT + fp] + bD[f]*oW[(FEAT+f)*FEAT + fp];
}

// transpose fp32 [K][N] -> fp16 [N][K]
__global__ void k_tsplit(const float* __restrict__ W, __half* __restrict__ B2,
                         int K, int N) {
    __shared__ float sm[32][33];
    int k0 = blockIdx.x*32, n0 = blockIdx.y*32;
    int tx = threadIdx.x, ty = threadIdx.y;
    #pragma unroll
    for (int r = 0; r < 32; r += 8)
        sm[ty+r][tx] = W[(size_t)(k0+ty+r)*N + n0 + tx];
    __syncthreads();
    #pragma unroll
    for (int r = 0; r < 32; r += 8) {
        int n = n0 + ty + r, k = k0 + tx;
        B2[(size_t)n*K + k] = __float2half_rn(sm[tx][ty+r]);
    }
}

// ---------------- layernorm + adaln -> fp16 ----------------
__global__ void k_ln_b(const float* __restrict__ in,
                       __half* __restrict__ outp, int out_ld, int base,
                       int sh_off, int sc_off) {
    int row = blockIdx.x;
    int b = row >> 12;
    int tid = threadIdx.x;
    float4 v = *(const float4*)(in + (size_t)row*FEAT + tid*4);
    float s = v.x+v.y+v.z+v.w;
    float q = v.x*v.x + v.y*v.y + v.z*v.z + v.w*v.w;
    #pragma unroll
    for (int o = 16; o > 0; o >>= 1) {
        s += __shfl_down_sync(0xffffffffu, s, o);
        q += __shfl_down_sync(0xffffffffu, q, o);
    }
    __shared__ float ss[8], sq[8];
    __shared__ float mu_s, rs_s;
    int w = tid >> 5, ln = tid & 31;
    if (ln == 0) { ss[w] = s; sq[w] = q; }
    __syncthreads();
    if (tid == 0) {
        float S=0.f, Q=0.f;
        #pragma unroll
        for (int i = 0; i < 8; i++) { S += ss[i]; Q += sq[i]; }
        float mu  = S * (1.0f/FEAT);
        float var = Q * (1.0f/FEAT) - mu*mu;
        mu_s = mu; rs_s = rsqrtf(var + LN_EPS);
    }
    __syncthreads();
    float mu = mu_s, rs = rs_s;
    const float* ada = g_ada + b*C6F;
    int f = tid*4;
    float val[4] = {v.x, v.y, v.z, v.w};
    __half* o = outp + (size_t)row*out_ld + base + f;
    #pragma unroll
    for (int c = 0; c < 4; c++) {
        float hv = (val[c]-mu)*rs*(1.0f+ada[sc_off+f+c]) + ada[sh_off+f+c];
        o[c] = __float2half_rn(hv);
    }
}

// ---------------- SIMT 128x128x8 GEMM (setup-only: E = CtS @ oW) ----------------
__global__ void __launch_bounds__(256) gemm_simt(
    const float* __restrict__ A, int lda,
    const float* __restrict__ Bm, int ldb,
    float* __restrict__ C, int ldc, int K)
{
    __shared__ float As[8][128];
    __shared__ float Bs[8][128];
    int tid = threadIdx.x;
    int m0 = blockIdx.y * 128;
    int n0 = blockIdx.x * 128;
    int tx = tid & 15, ty = tid >> 4;
    float acc[8][8];
    #pragma unroll
    for (int i = 0; i < 8; i++)
        #pragma unroll
        for (int j = 0; j < 8; j++) acc[i][j] = 0.f;
    int aRow = tid >> 1;
    int aK   = (tid & 1) * 4;
    int bRow = tid >> 5;
    int bCol = (tid & 31) * 4;
    const float* Ap = A + (size_t)(m0 + aRow)*lda + aK;
    const float* Bp = Bm + (size_t)bRow*ldb + n0 + bCol;
    for (int k0 = 0; k0 < K; k0 += 8) {
        float4 av = *(const float4*)(Ap + k0);
        float4 bv = *(const float4*)(Bp + (size_t)k0*ldb);
        __syncthreads();
        As[aK+0][aRow]=av.x; As[aK+1][aRow]=av.y; As[aK+2][aRow]=av.z; As[aK+3][aRow]=av.w;
        *(float4*)(&Bs[bRow][bCol]) = bv;
        __syncthreads();
        #pragma unroll
        for (int kk = 0; kk < 8; kk++) {
            float af[8], bf[8];
            *(float4*)(af)   = *(const float4*)(&As[kk][ty*8]);
            *(float4*)(af+4) = *(const float4*)(&As[kk][ty*8+4]);
            *(float4*)(bf)   = *(const float4*)(&Bs[kk][tx*8]);
            *(float4*)(bf+4) = *(const float4*)(&Bs[kk][tx*8+4]);
            #pragma unroll
            for (int i = 0; i < 8; i++)
                #pragma unroll
                for (int j = 0; j < 8; j++)
                    acc[i][j] += af[i]*bf[j];
        }
    }
    #pragma unroll
    for (int i = 0; i < 8; i++) {
        int row = m0 + ty*8 + i;
        #pragma unroll
        for (int j4 = 0; j4 < 8; j4 += 4) {
            int col = n0 + tx*8 + j4;
            float4 o;
            o.x = acc[i][j4+0]; o.y = acc[i][j4+1]; o.z = acc[i][j4+2]; o.w = acc[i][j4+3];
            *(float4*)(C + (size_t)row*ldc + col) = o;
        }
    }
}

// ---------------- parallel S5 scan -> fp16 into g_acat ----------------
__global__ void __launch_bounds__(128) k_scan() {
    int bid = blockIdx.x;
    int d   = bid >> 8;
    int rem = bid & 255;
    int b = rem >> 6, n = rem & 63;
    int tid = threadIdx.x;
    float2 A = g_Abar[d*64 + n];
    const float* bur = g_bu + ((size_t)((d*2+0)*B_SZ + b)*STATE + n)*SEQ;
    const float* bui = g_bu + ((size_t)((d*2+1)*B_SZ + b)*STATE + n)*SEQ;

    float xr[32], xi[32];
    float cr = 0.f, ci = 0.f;
    #pragma unroll
    for (int j = 0; j < 32; j++) {
        int i = tid*32 + j;
        int s = d ? (SEQ-1-i) : i;
        float ur = bur[s], ui = bui[s];
        float nr = A.x*cr - A.y*ci + ur;
        float ni = A.x*ci + A.y*cr + ui;
        cr = nr; ci = ni; xr[j] = cr; xi[j] = ci;
    }
    __shared__ float sr[128], si[128];
    sr[tid] = cr; si[tid] = ci;
    __syncthreads();
    float mr = A.x, mi = A.y;
    #pragma unroll
    for (int e = 0; e < 5; e++) { float t = mr*mr - mi*mi; mi = 2.f*mr*mi; mr = t; }
    for (int off = 1; off < 128; off <<= 1) {
        float c0 = sr[tid], c1 = si[tid];
        float p0 = 0.f, p1 = 0.f;
        if (tid >= off) { p0 = sr[tid-off]; p1 = si[tid-off]; }
        __syncthreads();
        sr[tid] = c0 + mr*p0 - mi*p1;
        si[tid] = c1 + mr*p1 + mi*p0;
        __syncthreads();
        float t = mr*mr - mi*mi; mi = 2.f*mr*mi; mr = t;
    }
    float pr = 0.f, pi = 0.f;
    if (tid > 0) { pr = sr[tid-1]; pi = si[tid-1]; }

    int col_r = d*128 + n;
    int col_i = d*128 + 64 + n;
    #pragma unroll
    for (int j = 0; j < 32; j++) {
        float t0 = A.x*pr - A.y*pi;
        float t1 = A.x*pi + A.y*pr;
        pr = t0; pi = t1;
        float vr = xr[j] + pr;
        float vi = xi[j] + pi;
        int i = tid*32 + j;
        int s = d ? (SEQ-1-i) : i;
        size_t rowb = (size_t)(b*SEQ + s)*1280;
        g_acat[rowb + col_r] = __float2half_rn(vr);
        g_acat[rowb + col_i] = __float2half_rn(vi);
    }
}

// ---------------- HMMA fp16 GEMM: 128x256 tile, mma m16n8k16, fp32 accum --------
constexpr int EPI_BU   = 1;   // planar bu store (fp32)
constexpr int EPI_MAIN = 2;   // Cf = aux1 + gate*(acc+bias)
constexpr int EPI_GELU = 3;   // Ch fp16 = gelu(acc+bias)
constexpr int EPI_OUT  = 4;   // Cf = aux1 + gate*(acc+bias)

// smem: 2 stages x (A 128x64 fp16 = 16KB | B 256x64 fp16 = 32KB) = 96KB
#define TG_SMEM 98304

template<int EPI>
__global__ void __launch_bounds__(256, 1)
tgemm(const __half* __restrict__ A2, int lda, int a0, int Ksec,
      const __half* __restrict__ Bm,
      float* __restrict__ Cf, __half* __restrict__ Ch,
      const float* __restrict__ bias,
      const float* __restrict__ aux1, const float* __restrict__ aux2)
{
    extern __shared__ __align__(1024) char smem[];
    const uint32_t sb = smem_u32(smem);
    const int tid = threadIdx.x, wid = tid >> 5, lane = tid & 31;
    const int m0 = blockIdx.y * 128, n0 = blockIdx.x * 256;
    const int wm = wid >> 2, wn = wid & 3;       // 2 x 4 warp grid; warp tile 64x64
    const int Ptot = Ksec >> 6;

    float acc[32][4];
    #pragma unroll
    for (int i = 0; i < 32; i++)
        #pragma unroll
        for (int j = 0; j < 4; j++) acc[i][j] = 0.f;

    // loader: A 2 thr/row (4x16B each), B 1 thr/row (8x16B each)
    const int ar = tid >> 1, ac0 = (tid & 1)*4;
    const char* Abase = (const char*)(A2 + (size_t)(m0 + ar)*lda + a0);
    const char* Bbase = (const char*)(Bm + (size_t)(n0 + tid)*Ksec);

    auto issue = [&](int p){
        uint32_t as_ = sb + (p & 1)*49152;
        uint32_t bs_ = as_ + 16384;
        const char* Asrc = Abase + (size_t)(p*64 + ac0*8)*2;
        const char* Bsrc = Bbase + (size_t)(p*64)*2;
        #pragma unroll
        for (int i = 0; i < 4; i++) {
            uint32_t off = ar*128 + (ac0+i)*16;
            cp16(as_ + SW128(off), Asrc + i*16);
        }
        #pragma unroll
        for (int i = 0; i < 8; i++) {
            uint32_t off = tid*128 + i*16;
            cp16(bs_ + SW128(off), Bsrc + i*16);
        }
        asm volatile("cp.async.commit_group;" ::: "memory");
    };

    issue(0);
    #pragma unroll 1
    for (int p = 0; p < Ptot; p++) {
        if (p + 1 < Ptot) {
            issue(p+1);
            asm volatile("cp.async.wait_group 1;" ::: "memory");
        } else {
            asm volatile("cp.async.wait_group 0;" ::: "memory");
        }
        __syncthreads();
        uint32_t as_ = sb + (p & 1)*49152;
        uint32_t bs_ = as_ + 16384;
        #pragma unroll
        for (int ks = 0; ks < 4; ks++) {
            uint32_t Af[4][4], Bf[4][4];
            #pragma unroll
            for (int mi = 0; mi < 4; mi++) {
                uint32_t off = (uint32_t)(wm*64 + mi*16 + (lane & 15))*128
                             + ks*32 + (lane >> 4)*16;
                uint32_t ad = as_ + SW128(off);
                asm volatile("ldmatrix.sync.aligned.m8n8.x4.shared.b16 {%0,%1,%2,%3}, [%4];"
                    : "=r"(Af[mi][0]), "=r"(Af[mi][1]), "=r"(Af[mi][2]), "=r"(Af[mi][3])
                    : "r"(ad));
            }
            #pragma unroll
            for (int nh = 0; nh < 4; nh++) {
                int n = wn*64 + nh*16 + ((lane >> 4) & 1)*8 + (lane & 7);
                uint32_t off = (uint32_t)n*128 + ks*32 + ((lane >> 3) & 1)*16;
                uint32_t ad = bs_ + SW128(off);
                asm volatile("ldmatrix.sync.aligned.m8n8.x4.shared.b16 {%0,%1,%2,%3}, [%4];"
                    : "=r"(Bf[nh][0]), "=r"(Bf[nh][1]), "=r"(Bf[nh][2]), "=r"(Bf[nh][3])
                    : "r"(ad));
            }
            #pragma unroll
            for (int mi = 0; mi < 4; mi++)
                #pragma unroll
                for (int nj = 0; nj < 8; nj++) {
                    float* c = acc[mi*8 + nj];
                    uint32_t b0 = Bf[nj>>1][(nj&1)*2], b1 = Bf[nj>>1][(nj&1)*2+1];
                    asm volatile(
                        "mma.sync.aligned.m16n8k16.row.col.f32.f16.f16.f32 "
                        "{%0,%1,%2,%3}, {%4,%5,%6,%7}, {%8,%9}, {%0,%1,%2,%3};"
                        : "+f"(c[0]), "+f"(c[1]), "+f"(c[2]), "+f"(c[3])
                        : "r"(Af[mi][0]), "r"(Af[mi][1]), "r"(Af[mi][2]), "r"(Af[mi][3]),
                          "r"(b0), "r"(b1));
                }
        }
        __syncthreads();
    }

    // ---- epilogue from fragments ----
    #pragma unroll
    for (int mi = 0; mi < 4; mi++) {
        #pragma unroll
        for (int nj = 0; nj < 8; nj++) {
            float* a = acc[mi*8 + nj];
            int r0 = m0 + wm*64 + mi*16 + (lane >> 2);
            int c  = n0 + wn*64 + nj*8 + (lane & 3)*2;
            #pragma unroll
            for (int h = 0; h < 2; h++) {
                int row = r0 + h*8;
                float v0 = a[h*2+0], v1 = a[h*2+1];
                if (EPI == EPI_BU) {
                    int srow = row & 4095, bb = row >> 12;
                    Cf[(((size_t)((c  )>>6)*B_SZ + bb)*STATE + ((c  )&63))*SEQ + srow] = v0;
                    Cf[(((size_t)((c+1)>>6)*B_SZ + bb)*STATE + ((c+1)&63))*SEQ + srow] = v1;
                } else if (EPI == EPI_GELU) {
                    float t0 = v0 + bias[c],   t1 = v1 + bias[c+1];
                    float u0 = 0.7978845608028654f*(t0 + 0.044715f*t0*t0*t0);
                    float u1 = 0.7978845608028654f*(t1 + 0.044715f*t1*t1*t1);
                    float g0 = 0.5f*t0*(1.0f + tanhf(u0));
                    float g1 = 0.5f*t1*(1.0f + tanhf(u1));
                    *(__half2*)(Ch + (size_t)row*HIDN + c) =
                        __half2{__float2half_rn(g0), __float2half_rn(g1)};
                } else {
                    int bb = row >> 12;
                    float g0 = aux2[bb*C6F + c], g1 = aux2[bb*C6F + c + 1];
                    float2 ax = *(const float2*)(aux1 + (size_t)row*FEAT + c);
                    float2 o;
                    o.x = ax.x + g0*(v0 + bias[c]);
                    o.y = ax.y + g1*(v1 + bias[c+1]);
                    *(float2*)(Cf + (size_t)row*FEAT + c) = o;
                }
            }
        }
    }
}

// ---------------- launch ----------------
extern "C" void kernel_launch(void* const* d_in, const int* in_sizes, int n_in,
                              void* d_out, int out_size) {
    const float* x    = (const float*)d_in[0];
    const float* cond = (const float*)d_in[1];
    const float* adaW = (const float*)d_in[2];
    const float* adab = (const float*)d_in[3];
    const float *fLA, *fAi, *fBr, *fBi, *fCr, *fCi, *fD, *fdt;
    const float *bLA, *bAi, *bBr, *bBi, *bCr, *bCi, *bD, *bdt;
    const float *oW, *ob, *W1, *b1, *W2, *b2;
    if (in_sizes[4] == STATE) {
        fLA=(const float*)d_in[4];  fAi=(const float*)d_in[5];
        fBr=(const float*)d_in[6];  fBi=(const float*)d_in[7];
        fCr=(const float*)d_in[8];  fCi=(const float*)d_in[9];
        fD =(const float*)d_in[10]; fdt=(const float*)d_in[11];
        bLA=(const float*)d_in[12]; bAi=(const float*)d_in[13];
        bBr=(const float*)d_in[14]; bBi=(const float*)d_in[15];
        bCr=(const float*)d_in[16]; bCi=(const float*)d_in[17];
        bD =(const float*)d_in[18]; bdt=(const float*)d_in[19];
        oW =(const float*)d_in[20]; ob =(const float*)d_in[21];
        W1 =(const float*)d_in[22]; b1 =(const float*)d_in[23];
        W2 =(const float*)d_in[24]; b2 =(const float*)d_in[25];
    } else {
        oW =(const float*)d_in[4];  ob =(const float*)d_in[5];
        W1 =(const float*)d_in[6];  b1 =(const float*)d_in[7];
        W2 =(const float*)d_in[8];  b2 =(const float*)d_in[9];
        fLA=(const float*)d_in[11]; fAi=(const float*)d_in[12];
        fBr=(const float*)d_in[13]; fBi=(const float*)d_in[14];
        fCr=(const float*)d_in[15]; fCi=(const float*)d_in[16];
        fD =(const float*)d_in[17]; fdt=(const float*)d_in[18];
        bLA=(const float*)d_in[19]; bAi=(const float*)d_in[20];
        bBr=(const float*)d_in[21]; bBi=(const float*)d_in[22];
        bCr=(const float*)d_in[23]; bCi=(const float*)d_in[24];
        bD =(const float*)d_in[25]; bdt=(const float*)d_in[26];
    }
    float* out = (float*)d_out;

    float *pXmid, *pBu, *pAda, *pWp, *pWcat, *pCtS;
    __half *pAcat, *pH2, *pHid, *pWp2, *pWcat2, *pW12, *pW22;
    cudaGetSymbolAddress((void**)&pXmid, g_xmid);
    cudaGetSymbolAddress((void**)&pBu,   g_bu);
    cudaGetSymbolAddress((void**)&pAda,  g_ada);
    cudaGetSymbolAddress((void**)&pWp,   g_Wp);
    cudaGetSymbolAddress((void**)&pWcat, g_Wcat);
    cudaGetSymbolAddress((void**)&pCtS,  g_CtS);
    cudaGetSymbolAddress((void**)&pAcat, g_acat);
    cudaGetSymbolAddress((void**)&pH2,   g_h2);
    cudaGetSymbolAddress((void**)&pHid,  g_hid);
    cudaGetSymbolAddress((void**)&pWp2,  g_wp2);
    cudaGetSymbolAddress((void**)&pWcat2,g_wcat2);
    cudaGetSymbolAddress((void**)&pW12,  g_w12);
    cudaGetSymbolAddress((void**)&pW22,  g_w22);

    cudaFuncSetAttribute(tgemm<EPI_BU>,   cudaFuncAttributeMaxDynamicSharedMemorySize, TG_SMEM);
    cudaFuncSetAttribute(tgemm<EPI_MAIN>, cudaFuncAttributeMaxDynamicSharedMemorySize, TG_SMEM);
    cudaFuncSetAttribute(tgemm<EPI_GELU>, cudaFuncAttributeMaxDynamicSharedMemorySize, TG_SMEM);
    cudaFuncSetAttribute(tgemm<EPI_OUT>,  cudaFuncAttributeMaxDynamicSharedMemorySize, TG_SMEM);

    // ---- setup / precompute (fp32) ----
    k_coef<<<1,128>>>(fLA, fAi, fdt, bLA, bAi, bdt);
    k_silu<<<(B_SZ*FEAT+255)/256,256>>>(cond);
    k_ada<<<C6F/256,256>>>(adaW, adab);
    k_wp<<<(FEAT*256)/256,256>>>(fBr, fBi, bBr, bBi);
    k_cts<<<(256*FEAT)/256,256>>>(fCr, fCi, bCr, bCi);
    k_G<<<(FEAT*FEAT)/256,256>>>(fD, bD, oW);
    // E = CtS @ out_W halves -> g_Wcat rows 0:256
    gemm_simt<<<dim3(8,1),256>>>(pCtS, FEAT, oW, FEAT, pWcat, FEAT, FEAT);
    gemm_simt<<<dim3(8,1),256>>>(pCtS + 128*FEAT, FEAT, oW + FEAT*FEAT, FEAT,
                                 pWcat + 128*FEAT, FEAT, FEAT);
    // ---- weight transpose to fp16 [N][K] ----
    dim3 tb(32,8);
    k_tsplit<<<dim3(FEAT/32, 256/32), tb>>>(pWp,   pWp2,   FEAT, 256);
    k_tsplit<<<dim3(KCAT/32, FEAT/32), tb>>>(pWcat, pWcat2, KCAT, FEAT);
    k_tsplit<<<dim3(FEAT/32, HIDN/32), tb>>>(W1,    pW12,   FEAT, HIDN);
    k_tsplit<<<dim3(HIDN/32, FEAT/32), tb>>>(W2,    pW22,   HIDN, FEAT);

    // ---- main pipeline ----
    // LN1 -> h portion of Acat (cols 256:1280)
    k_ln_b<<<BS,256>>>(x, pAcat, 1280, 256, /*sh1*/0, /*sc1*/FEAT);
    // Bu = h @ Wp   (N=256 -> one tile wide)
    tgemm<EPI_BU><<<dim3(1, BS/128), 256, TG_SMEM>>>(
        pAcat, 1280, 256, FEAT, pWp2,
        pBu, nullptr, nullptr, nullptr, nullptr);
    k_scan<<<512,128>>>();
    // xmid = x + g1*( [xs|h] @ Wcat + ob )
    tgemm<EPI_MAIN><<<dim3(FEAT/256, BS/128), 256, TG_SMEM>>>(
        pAcat, 1280, 0, KCAT, pWcat2,
        pXmid, nullptr, ob, x, pAda + 2*FEAT);
    // LN2 -> h2
    k_ln_b<<<BS,256>>>(pXmid, pH2, 1024, 0, /*sh2*/3*FEAT, /*sc2*/4*FEAT);
    // hid = gelu(h2 @ W1 + b1)
    tgemm<EPI_GELU><<<dim3(HIDN/256, BS/128), 256, TG_SMEM>>>(
        pH2, 1024, 0, FEAT, pW12,
        nullptr, pHid, b1, nullptr, nullptr);
    // out = xmid + g2*( hid @ W2 + b2 )
    tgemm<EPI_OUT><<<dim3(FEAT/256, BS/128), 256, TG_SMEM>>>(
        pHid, 4096, 0, HIDN, pW22,
        out, nullptr, b2, pXmid, pAda + 5*FEAT);
    (void)n_in; (void)out_size;
}

// round 11
// speedup vs baseline: 1.8995x; 1.8995x over previous
#include <cuda_runtime.h>
#include <cuda_bf16.h>
#include <cuda_fp16.h>
#include <math.h>
#include <stdint.h>

#define B_SZ  4
#define SEQ   4096
#define FEAT  1024
#define STATE 64
#define HIDN  4096
#define BS    (B_SZ*SEQ)      /* 16384 */
#define C6F   (6*FEAT)        /* 6144  */
#define KCAT  (256+FEAT)      /* 1280  */
#define LN_EPS 1e-5f

// ---------------- scratch (device globals; no allocation allowed) ----------------
__device__ float  g_bu[2*2*B_SZ*STATE*SEQ];           // [(d*2+p)][b][n][s] fp32
__device__ float  g_xmid[BS*FEAT];
__device__ float  g_ada[B_SZ*C6F];
__device__ float  g_silu[B_SZ*FEAT];
__device__ float  g_Wp[FEAT*256];                     // fp32 [K=1024][N=256]
__device__ float  g_Wcat[KCAT*FEAT];                  // fp32 [K=1280][N=1024]; rows 0:256=E, 256:1280=G
__device__ float  g_CtS[256*FEAT];
__device__ float2 g_Abar[2*STATE];
__device__ float2 g_coef[2*STATE];
// fp16 activation / weight buffers
__device__ __half g_acat[(size_t)BS*1280];     // [row][1280] = [xs(256)|h(1024)]
__device__ __half g_h2  [(size_t)BS*1024];     // [row][1024]
__device__ __half g_hid [(size_t)BS*4096];     // [row][4096]
__device__ __half g_wp2 [256*1024];            // [N=256][K=1024]
__device__ __half g_wcat2[(size_t)1024*1280];  // [N=1024][K=1280]
__device__ __half g_w12 [(size_t)4096*1024];   // [N=4096][K=1024]
__device__ __half g_w22 [(size_t)1024*4096];   // [N=1024][K=4096]

// ---------------- helpers ----------------
__device__ __forceinline__ uint32_t smem_u32(const void* p){
    uint32_t a; asm("{ .reg .u64 t; cvta.to.shared.u64 t, %1; cvt.u32.u64 %0, t; }":"=r"(a):"l"(p)); return a;
}
__device__ __forceinline__ void cp16(uint32_t dst, const void* src){
    asm volatile("cp.async.cg.shared.global [%0], [%1], 16;"::"r"(dst),"l"(src):"memory");
}
#define SW128(o) ((o) ^ (((o)>>3)&0x70))

// ---------------- small setup kernels ----------------
__global__ void k_coef(const float* fLA, const float* fAi, const float* fdt,
                       const float* bLA, const float* bAi, const float* bdt) {
    int t = threadIdx.x;
    if (t >= 128) return;
    int d = t >> 6, n = t & 63;
    const float* LA  = d ? bLA : fLA;
    const float* Ai  = d ? bAi : fAi;
    const float* LDT = d ? bdt : fdt;
    float dt = expf(LDT[n]);
    float ar = -expf(LA[n]);
    float ai = Ai[n];
    float e  = expf(ar*dt);
    float Abr = e*cosf(ai*dt);
    float Abi = e*sinf(ai*dt);
    float dr = ar + 1e-8f, di = ai;
    float den = dr*dr + di*di;
    float nr = Abr - 1.0f, ni = Abi;
    g_Abar[t] = make_float2(Abr, Abi);
    g_coef[t] = make_float2((nr*dr + ni*di)/den, (ni*dr - nr*di)/den);
}

__global__ void k_silu(const float* __restrict__ cond) {
    int i = blockIdx.x*256 + threadIdx.x;
    if (i < B_SZ*FEAT) { float c = cond[i]; g_silu[i] = c / (1.0f + expf(-c)); }
}

__global__ void k_ada(const float* __restrict__ W, const float* __restrict__ bias) {
    __shared__ float sc[B_SZ*FEAT];
    int tid = threadIdx.x;
    for (int i = tid; i < B_SZ*FEAT; i += 256) sc[i] = g_silu[i];
    __syncthreads();
    int col = blockIdx.x*256 + tid;
    float a0=0.f, a1=0.f, a2=0.f, a3=0.f;
    for (int k = 0; k < FEAT; k++) {
        float w = W[k*C6F + col];
        a0 += sc[k]*w; a1 += sc[FEAT+k]*w; a2 += sc[2*FEAT+k]*w; a3 += sc[3*FEAT+k]*w;
    }
    float bb = bias[col];
    g_ada[col]       = a0 + bb;
    g_ada[C6F+col]   = a1 + bb;
    g_ada[2*C6F+col] = a2 + bb;
    g_ada[3*C6F+col] = a3 + bb;
}

__global__ void k_wp(const float* fBr, const float* fBi, const float* bBr, const float* bBi) {
    int idx = blockIdx.x*256 + threadIdx.x;   // FEAT*256
    int c = idx & 255, f = idx >> 8;
    int d = c >> 7, p = (c >> 6) & 1, n = c & 63;
    float2 co = g_coef[d*64 + n];
    const float* Br = d ? bBr : fBr;
    const float* Bi = d ? bBi : fBi;
    float br = Br[n*FEAT + f], bi = Bi[n*FEAT + f];
    g_Wp[idx] = p ? (co.x*bi + co.y*br) : (co.x*br - co.y*bi);
}

__global__ void k_cts(const float* fCr, const float* fCi, const float* bCr, const float* bCi) {
    int idx = blockIdx.x*256 + threadIdx.x;   // 256*FEAT
    int f = idx & (FEAT-1), c = idx >> 10;
    int d = c >> 7, p = (c >> 6) & 1, n = c & 63;
    const float* Cp = p ? (d ? bCi : fCi) : (d ? bCr : fCr);
    float v = Cp[f*STATE + n];
    g_CtS[idx] = p ? -v : v;
}

__global__ void k_G(const float* fD, const float* bD, const float* oW) {
    int idx = blockIdx.x*256 + threadIdx.x;   // FEAT*FEAT
    int fp = idx & (FEAT-1), f = idx >> 10;
    g_Wcat[(256+f)*FEAT + fp] = fD[f]*oW[f*FEAT + fp] + bD[f]*oW[(FEAT+f)*FEAT + fp];
}

// transpose fp32 [K][N] -> fp16 [N][K]
__global__ void k_tsplit(const float* __restrict__ W, __half* __restrict__ B2,
                         int K, int N) {
    __shared__ float sm[32][33];
    int k0 = blockIdx.x*32, n0 = blockIdx.y*32;
    int tx = threadIdx.x, ty = threadIdx.y;
    #pragma unroll
    for (int r = 0; r < 32; r += 8)
        sm[ty+r][tx] = W[(size_t)(k0+ty+r)*N + n0 + tx];
    __syncthreads();
    #pragma unroll
    for (int r = 0; r < 32; r += 8) {
        int n = n0 + ty + r, k = k0 + tx;
        B2[(size_t)n*K + k] = __float2half_rn(sm[tx][ty+r]);
    }
}

// ---------------- layernorm + adaln -> fp16 ----------------
__global__ void k_ln_b(const float* __restrict__ in,
                       __half* __restrict__ outp, int out_ld, int base,
                       int sh_off, int sc_off) {
    int row = blockIdx.x;
    int b = row >> 12;
    int tid = threadIdx.x;
    float4 v = *(const float4*)(in + (size_t)row*FEAT + tid*4);
    float s = v.x+v.y+v.z+v.w;
    float q = v.x*v.x + v.y*v.y + v.z*v.z + v.w*v.w;
    #pragma unroll
    for (int o = 16; o > 0; o >>= 1) {
        s += __shfl_down_sync(0xffffffffu, s, o);
        q += __shfl_down_sync(0xffffffffu, q, o);
    }
    __shared__ float ss[8], sq[8];
    __shared__ float mu_s, rs_s;
    int w = tid >> 5, ln = tid & 31;
    if (ln == 0) { ss[w] = s; sq[w] = q; }
    __syncthreads();
    if (tid == 0) {
        float S=0.f, Q=0.f;
        #pragma unroll
        for (int i = 0; i < 8; i++) { S += ss[i]; Q += sq[i]; }
        float mu  = S * (1.0f/FEAT);
        float var = Q * (1.0f/FEAT) - mu*mu;
        mu_s = mu; rs_s = rsqrtf(var + LN_EPS);
    }
    __syncthreads();
    float mu = mu_s, rs = rs_s;
    const float* ada = g_ada + b*C6F;
    int f = tid*4;
    float val[4] = {v.x, v.y, v.z, v.w};
    __half* o = outp + (size_t)row*out_ld + base + f;
    #pragma unroll
    for (int c = 0; c < 4; c++) {
        float hv = (val[c]-mu)*rs*(1.0f+ada[sc_off+f+c]) + ada[sh_off+f+c];
        o[c] = __float2half_rn(hv);
    }
}

// ---------------- SIMT 128x128x8 GEMM (setup-only: E = CtS @ oW) ----------------
__global__ void __launch_bounds__(256) gemm_simt(
    const float* __restrict__ A, int lda,
    const float* __restrict__ Bm, int ldb,
    float* __restrict__ C, int ldc, int K)
{
    __shared__ float As[8][128];
    __shared__ float Bs[8][128];
    int tid = threadIdx.x;
    int m0 = blockIdx.y * 128;
    int n0 = blockIdx.x * 128;
    int tx = tid & 15, ty = tid >> 4;
    float acc[8][8];
    #pragma unroll
    for (int i = 0; i < 8; i++)
        #pragma unroll
        for (int j = 0; j < 8; j++) acc[i][j] = 0.f;
    int aRow = tid >> 1;
    int aK   = (tid & 1) * 4;
    int bRow = tid >> 5;
    int bCol = (tid & 31) * 4;
    const float* Ap = A + (size_t)(m0 + aRow)*lda + aK;
    const float* Bp = Bm + (size_t)bRow*ldb + n0 + bCol;
    for (int k0 = 0; k0 < K; k0 += 8) {
        float4 av = *(const float4*)(Ap + k0);
        float4 bv = *(const float4*)(Bp + (size_t)k0*ldb);
        __syncthreads();
        As[aK+0][aRow]=av.x; As[aK+1][aRow]=av.y; As[aK+2][aRow]=av.z; As[aK+3][aRow]=av.w;
        *(float4*)(&Bs[bRow][bCol]) = bv;
        __syncthreads();
        #pragma unroll
        for (int kk = 0; kk < 8; kk++) {
            float af[8], bf[8];
            *(float4*)(af)   = *(const float4*)(&As[kk][ty*8]);
            *(float4*)(af+4) = *(const float4*)(&As[kk][ty*8+4]);
            *(float4*)(bf)   = *(const float4*)(&Bs[kk][tx*8]);
            *(float4*)(bf+4) = *(const float4*)(&Bs[kk][tx*8+4]);
            #pragma unroll
            for (int i = 0; i < 8; i++)
                #pragma unroll
                for (int j = 0; j < 8; j++)
                    acc[i][j] += af[i]*bf[j];
        }
    }
    #pragma unroll
    for (int i = 0; i < 8; i++) {
        int row = m0 + ty*8 + i;
        #pragma unroll
        for (int j4 = 0; j4 < 8; j4 += 4) {
            int col = n0 + tx*8 + j4;
            float4 o;
            o.x = acc[i][j4+0]; o.y = acc[i][j4+1]; o.z = acc[i][j4+2]; o.w = acc[i][j4+3];
            *(float4*)(C + (size_t)row*ldc + col) = o;
        }
    }
}

// ---------------- parallel S5 scan -> fp16 into g_acat ----------------
__global__ void __launch_bounds__(128) k_scan() {
    int bid = blockIdx.x;
    int d   = bid >> 8;
    int rem = bid & 255;
    int b = rem >> 6, n = rem & 63;
    int tid = threadIdx.x;
    float2 A = g_Abar[d*64 + n];
    const float* bur = g_bu + ((size_t)((d*2+0)*B_SZ + b)*STATE + n)*SEQ;
    const float* bui = g_bu + ((size_t)((d*2+1)*B_SZ + b)*STATE + n)*SEQ;

    float xr[32], xi[32];
    float cr = 0.f, ci = 0.f;
    #pragma unroll
    for (int j = 0; j < 32; j++) {
        int i = tid*32 + j;
        int s = d ? (SEQ-1-i) : i;
        float ur = bur[s], ui = bui[s];
        float nr = A.x*cr - A.y*ci + ur;
        float ni = A.x*ci + A.y*cr + ui;
        cr = nr; ci = ni; xr[j] = cr; xi[j] = ci;
    }
    __shared__ float sr[128], si[128];
    sr[tid] = cr; si[tid] = ci;
    __syncthreads();
    float mr = A.x, mi = A.y;
    #pragma unroll
    for (int e = 0; e < 5; e++) { float t = mr*mr - mi*mi; mi = 2.f*mr*mi; mr = t; }
    for (int off = 1; off < 128; off <<= 1) {
        float c0 = sr[tid], c1 = si[tid];
        float p0 = 0.f, p1 = 0.f;
        if (tid >= off) { p0 = sr[tid-off]; p1 = si[tid-off]; }
        __syncthreads();
        sr[tid] = c0 + mr*p0 - mi*p1;
        si[tid] = c1 + mr*p1 + mi*p0;
        __syncthreads();
        float t = mr*mr - mi*mi; mi = 2.f*mr*mi; mr = t;
    }
    float pr = 0.f, pi = 0.f;
    if (tid > 0) { pr = sr[tid-1]; pi = si[tid-1]; }

    int col_r = d*128 + n;
    int col_i = d*128 + 64 + n;
    #pragma unroll
    for (int j = 0; j < 32; j++) {
        float t0 = A.x*pr - A.y*pi;
        float t1 = A.x*pi + A.y*pr;
        pr = t0; pi = t1;
        float vr = xr[j] + pr;
        float vi = xi[j] + pi;
        int i = tid*32 + j;
        int s = d ? (SEQ-1-i) : i;
        size_t rowb = (size_t)(b*SEQ + s)*1280;
        g_acat[rowb + col_r] = __float2half_rn(vr);
        g_acat[rowb + col_i] = __float2half_rn(vi);
    }
}

// ---------------- HMMA fp16 GEMM: 128x128 tile, 3-stage cp.async pipeline -------
constexpr int EPI_BU   = 1;   // planar bu store (fp32)
constexpr int EPI_MAIN = 2;   // Cf = aux1 + gate*(acc+bias)
constexpr int EPI_GELU = 3;   // Ch fp16 = gelu(acc+bias)
constexpr int EPI_OUT  = 4;   // Cf = aux1 + gate*(acc+bias)

// smem: 3 stages x (A 128x64 fp16 = 16KB | B 128x64 fp16 = 16KB) = 96KB
#define TG_SMEM 98304

template<int EPI>
__global__ void __launch_bounds__(256)
tgemm(const __half* __restrict__ A2, int lda, int a0, int Ksec,
      const __half* __restrict__ Bm,
      float* __restrict__ Cf, __half* __restrict__ Ch,
      const float* __restrict__ bias,
      const float* __restrict__ aux1, const float* __restrict__ aux2)
{
    extern __shared__ __align__(1024) char smem[];
    const uint32_t sb = smem_u32(smem);
    const int tid = threadIdx.x, wid = tid >> 5, lane = tid & 31;
    const int m0 = blockIdx.y * 128, n0 = blockIdx.x * 128;
    const int wm = wid >> 2, wn = wid & 3;       // 2 x 4 warp grid; warp tile 64x32
    const int Ptot = Ksec >> 6;

    float acc[16][4];
    #pragma unroll
    for (int i = 0; i < 16; i++)
        #pragma unroll
        for (int j = 0; j < 4; j++) acc[i][j] = 0.f;

    // loader mapping: 256 thr; each loads 4x16B for A and 4x16B for B
    const int ar = tid >> 1, ac0 = (tid & 1)*4;
    const char* Abase = (const char*)(A2 + (size_t)(m0 + ar)*lda + a0);
    const char* Bbase = (const char*)(Bm + (size_t)(n0 + ar)*Ksec);

    auto stage_of = [&](int p){ int s = p % 3; return sb + (uint32_t)s*32768; };

    auto issue = [&](int p){
        uint32_t as_ = stage_of(p);
        uint32_t bs_ = as_ + 16384;
        const char* Asrc = Abase + (size_t)(p*64 + ac0*8)*2;
        const char* Bsrc = Bbase + (size_t)(p*64 + ac0*8)*2;
        #pragma unroll
        for (int i = 0; i < 4; i++) {
            uint32_t off = ar*128 + (ac0+i)*16;
            uint32_t sw = SW128(off);
            cp16(as_ + sw, Asrc + i*16);
            cp16(bs_ + sw, Bsrc + i*16);
        }
        asm volatile("cp.async.commit_group;" ::: "memory");
    };

    issue(0);
    if (Ptot > 1) issue(1);
    #pragma unroll 1
    for (int p = 0; p < Ptot; p++) {
        if (p + 2 < Ptot) {
            issue(p+2);
            asm volatile("cp.async.wait_group 2;" ::: "memory");
        } else if (p + 1 < Ptot) {
            asm volatile("cp.async.wait_group 1;" ::: "memory");
        } else {
            asm volatile("cp.async.wait_group 0;" ::: "memory");
        }
        __syncthreads();
        uint32_t as_ = stage_of(p);
        uint32_t bs_ = as_ + 16384;
        #pragma unroll
        for (int ks = 0; ks < 4; ks++) {
            uint32_t Af[4][4], Bf[2][4];
            #pragma unroll
            for (int mi = 0; mi < 4; mi++) {
                uint32_t off = (uint32_t)(wm*64 + mi*16 + (lane & 15))*128
                             + ks*32 + (lane >> 4)*16;
                uint32_t ad = as_ + SW128(off);
                asm volatile("ldmatrix.sync.aligned.m8n8.x4.shared.b16 {%0,%1,%2,%3}, [%4];"
                    : "=r"(Af[mi][0]), "=r"(Af[mi][1]), "=r"(Af[mi][2]), "=r"(Af[mi][3])
                    : "r"(ad));
            }
            #pragma unroll
            for (int nh = 0; nh < 2; nh++) {
                int n = wn*32 + nh*16 + ((lane >> 4) & 1)*8 + (lane & 7);
                uint32_t off = (uint32_t)n*128 + ks*32 + ((lane >> 3) & 1)*16;
                uint32_t ad = bs_ + SW128(off);
                asm volatile("ldmatrix.sync.aligned.m8n8.x4.shared.b16 {%0,%1,%2,%3}, [%4];"
                    : "=r"(Bf[nh][0]), "=r"(Bf[nh][1]), "=r"(Bf[nh][2]), "=r"(Bf[nh][3])
                    : "r"(ad));
            }
            #pragma unroll
            for (int mi = 0; mi < 4; mi++)
                #pragma unroll
                for (int nj = 0; nj < 4; nj++) {
                    float* c = acc[mi*4 + nj];
                    uint32_t b0 = Bf[nj>>1][(nj&1)*2], b1 = Bf[nj>>1][(nj&1)*2+1];
                    asm volatile(
                        "mma.sync.aligned.m16n8k16.row.col.f32.f16.f16.f32 "
                        "{%0,%1,%2,%3}, {%4,%5,%6,%7}, {%8,%9}, {%0,%1,%2,%3};"
                        : "+f"(c[0]), "+f"(c[1]), "+f"(c[2]), "+f"(c[3])
                        : "r"(Af[mi][0]), "r"(Af[mi][1]), "r"(Af[mi][2]), "r"(Af[mi][3]),
                          "r"(b0), "r"(b1));
                }
        }
        __syncthreads();
    }

    // ---- epilogue from fragments ----
    #pragma unroll
    for (int mi = 0; mi < 4; mi++) {
        #pragma unroll
        for (int nj = 0; nj < 4; nj++) {
            float* a = acc[mi*4 + nj];
            int r0 = m0 + wm*64 + mi*16 + (lane >> 2);
            int c  = n0 + wn*32 + nj*8 + (lane & 3)*2;
            #pragma unroll
            for (int h = 0; h < 2; h++) {
                int row = r0 + h*8;
                float v0 = a[h*2+0], v1 = a[h*2+1];
                if (EPI == EPI_BU) {
                    int srow = row & 4095, bb = row >> 12;
                    Cf[(((size_t)((c  )>>6)*B_SZ + bb)*STATE + ((c  )&63))*SEQ + srow] = v0;
                    Cf[(((size_t)((c+1)>>6)*B_SZ + bb)*STATE + ((c+1)&63))*SEQ + srow] = v1;
                } else if (EPI == EPI_GELU) {
                    float t0 = v0 + bias[c],   t1 = v1 + bias[c+1];
                    float u0 = 0.7978845608028654f*(t0 + 0.044715f*t0*t0*t0);
                    float u1 = 0.7978845608028654f*(t1 + 0.044715f*t1*t1*t1);
                    float g0 = 0.5f*t0*(1.0f + tanhf(u0));
                    float g1 = 0.5f*t1*(1.0f + tanhf(u1));
                    *(__half2*)(Ch + (size_t)row*HIDN + c) =
                        __half2{__float2half_rn(g0), __float2half_rn(g1)};
                } else {
                    int bb = row >> 12;
                    float g0 = aux2[bb*C6F + c], g1 = aux2[bb*C6F + c + 1];
                    float2 ax = *(const float2*)(aux1 + (size_t)row*FEAT + c);
                    float2 o;
                    o.x = ax.x + g0*(v0 + bias[c]);
                    o.y = ax.y + g1*(v1 + bias[c+1]);
                    *(float2*)(Cf + (size_t)row*FEAT + c) = o;
                }
            }
        }
    }
}

// ---------------- launch ----------------
extern "C" void kernel_launch(void* const* d_in, const int* in_sizes, int n_in,
                              void* d_out, int out_size) {
    const float* x    = (const float*)d_in[0];
    const float* cond = (const float*)d_in[1];
    const float* adaW = (const float*)d_in[2];
    const float* adab = (const float*)d_in[3];
    const float *fLA, *fAi, *fBr, *fBi, *fCr, *fCi, *fD, *fdt;
    const float *bLA, *bAi, *bBr, *bBi, *bCr, *bCi, *bD, *bdt;
    const float *oW, *ob, *W1, *b1, *W2, *b2;
    if (in_sizes[4] == STATE) {
        fLA=(const float*)d_in[4];  fAi=(const float*)d_in[5];
        fBr=(const float*)d_in[6];  fBi=(const float*)d_in[7];
        fCr=(const float*)d_in[8];  fCi=(const float*)d_in[9];
        fD =(const float*)d_in[10]; fdt=(const float*)d_in[11];
        bLA=(const float*)d_in[12]; bAi=(const float*)d_in[13];
        bBr=(const float*)d_in[14]; bBi=(const float*)d_in[15];
        bCr=(const float*)d_in[16]; bCi=(const float*)d_in[17];
        bD =(const float*)d_in[18]; bdt=(const float*)d_in[19];
        oW =(const float*)d_in[20]; ob =(const float*)d_in[21];
        W1 =(const float*)d_in[22]; b1 =(const float*)d_in[23];
        W2 =(const float*)d_in[24]; b2 =(const float*)d_in[25];
    } else {
        oW =(const float*)d_in[4];  ob =(const float*)d_in[5];
        W1 =(const float*)d_in[6];  b1 =(const float*)d_in[7];
        W2 =(const float*)d_in[8];  b2 =(const float*)d_in[9];
        fLA=(const float*)d_in[11]; fAi=(const float*)d_in[12];
        fBr=(const float*)d_in[13]; fBi=(const float*)d_in[14];
        fCr=(const float*)d_in[15]; fCi=(const float*)d_in[16];
        fD =(const float*)d_in[17]; fdt=(const float*)d_in[18];
        bLA=(const float*)d_in[19]; bAi=(const float*)d_in[20];
        bBr=(const float*)d_in[21]; bBi=(const float*)d_in[22];
        bCr=(const float*)d_in[23]; bCi=(const float*)d_in[24];
        bD =(const float*)d_in[25]; bdt=(const float*)d_in[26];
    }
    float* out = (float*)d_out;

    float *pXmid, *pBu, *pAda, *pWp, *pWcat, *pCtS;
    __half *pAcat, *pH2, *pHid, *pWp2, *pWcat2, *pW12, *pW22;
    cudaGetSymbolAddress((void**)&pXmid, g_xmid);
    cudaGetSymbolAddress((void**)&pBu,   g_bu);
    cudaGetSymbolAddress((void**)&pAda,  g_ada);
    cudaGetSymbolAddress((void**)&pWp,   g_Wp);
    cudaGetSymbolAddress((void**)&pWcat, g_Wcat);
    cudaGetSymbolAddress((void**)&pCtS,  g_CtS);
    cudaGetSymbolAddress((void**)&pAcat, g_acat);
    cudaGetSymbolAddress((void**)&pH2,   g_h2);
    cudaGetSymbolAddress((void**)&pHid,  g_hid);
    cudaGetSymbolAddress((void**)&pWp2,  g_wp2);
    cudaGetSymbolAddress((void**)&pWcat2,g_wcat2);
    cudaGetSymbolAddress((void**)&pW12,  g_w12);
    cudaGetSymbolAddress((void**)&pW22,  g_w22);

    cudaFuncSetAttribute(tgemm<EPI_BU>,   cudaFuncAttributeMaxDynamicSharedMemorySize, TG_SMEM);
    cudaFuncSetAttribute(tgemm<EPI_MAIN>, cudaFuncAttributeMaxDynamicSharedMemorySize, TG_SMEM);
    cudaFuncSetAttribute(tgemm<EPI_GELU>, cudaFuncAttributeMaxDynamicSharedMemorySize, TG_SMEM);
    cudaFuncSetAttribute(tgemm<EPI_OUT>,  cudaFuncAttributeMaxDynamicSharedMemorySize, TG_SMEM);

    // ---- setup / precompute (fp32) ----
    k_coef<<<1,128>>>(fLA, fAi, fdt, bLA, bAi, bdt);
    k_silu<<<(B_SZ*FEAT+255)/256,256>>>(cond);
    k_ada<<<C6F/256,256>>>(adaW, adab);
    k_wp<<<(FEAT*256)/256,256>>>(fBr, fBi, bBr, bBi);
    k_cts<<<(256*FEAT)/256,256>>>(fCr, fCi, bCr, bCi);
    k_G<<<(FEAT*FEAT)/256,256>>>(fD, bD, oW);
    // E = CtS @ out_W halves -> g_Wcat rows 0:256
    gemm_simt<<<dim3(8,1),256>>>(pCtS, FEAT, oW, FEAT, pWcat, FEAT, FEAT);
    gemm_simt<<<dim3(8,1),256>>>(pCtS + 128*FEAT, FEAT, oW + FEAT*FEAT, FEAT,
                                 pWcat + 128*FEAT, FEAT, FEAT);
    // ---- weight transpose to fp16 [N][K] ----
    dim3 tb(32,8);
    k_tsplit<<<dim3(FEAT/32, 256/32), tb>>>(pWp,   pWp2,   FEAT, 256);
    k_tsplit<<<dim3(KCAT/32, FEAT/32), tb>>>(pWcat, pWcat2, KCAT, FEAT);
    k_tsplit<<<dim3(FEAT/32, HIDN/32), tb>>>(W1,    pW12,   FEAT, HIDN);
    k_tsplit<<<dim3(HIDN/32, FEAT/32), tb>>>(W2,    pW22,   HIDN, FEAT);

    // ---- main pipeline ----
    // LN1 -> h portion of Acat (cols 256:1280)
    k_ln_b<<<BS,256>>>(x, pAcat, 1280, 256, /*sh1*/0, /*sc1*/FEAT);
    // Bu = h @ Wp
    tgemm<EPI_BU><<<dim3(2, BS/128), 256, TG_SMEM>>>(
        pAcat, 1280, 256, FEAT, pWp2,
        pBu, nullptr, nullptr, nullptr, nullptr);
    k_scan<<<512,128>>>();
    // xmid = x + g1*( [xs|h] @ Wcat + ob )
    tgemm<EPI_MAIN><<<dim3(FEAT/128, BS/128), 256, TG_SMEM>>>(
        pAcat, 1280, 0, KCAT, pWcat2,
        pXmid, nullptr, ob, x, pAda + 2*FEAT);
    // LN2 -> h2
    k_ln_b<<<BS,256>>>(pXmid, pH2, 1024, 0, /*sh2*/3*FEAT, /*sc2*/4*FEAT);
    // hid = gelu(h2 @ W1 + b1)
    tgemm<EPI_GELU><<<dim3(HIDN/128, BS/128), 256, TG_SMEM>>>(
        pH2, 1024, 0, FEAT, pW12,
        nullptr, pHid, b1, nullptr, nullptr);
    // out = xmid + g2*( hid @ W2 + b2 )
    tgemm<EPI_OUT><<<dim3(FEAT/128, BS/128), 256, TG_SMEM>>>(
        pHid, 4096, 0, HIDN, pW22,
        out, nullptr, b2, pXmid, pAda + 5*FEAT);
    (void)n_in; (void)out_size;
}

// round 12
// speedup vs baseline: 2.2339x; 1.1760x over previous
#include <cuda_runtime.h>
#include <cuda_bf16.h>
#include <cuda_fp16.h>
#include <math.h>
#include <stdint.h>

#define B_SZ  4
#define SEQ   4096
#define FEAT  1024
#define STATE 64
#define HIDN  4096
#define BS    (B_SZ*SEQ)      /* 16384 */
#define C6F   (6*FEAT)        /* 6144  */
#define KCAT  (256+FEAT)      /* 1280  */
#define LN_EPS 1e-5f

// ---------------- scratch (device globals; no allocation allowed) ----------------
__device__ float  g_bu[2*2*B_SZ*STATE*SEQ];           // [(d*2+p)][b][n][s] fp32 (Bu, then xs in-place)
__device__ float  g_xmid[BS*FEAT];
__device__ float  g_ada[B_SZ*C6F];
__device__ float  g_silu[B_SZ*FEAT];
__device__ float  g_Wp[FEAT*256];                     // fp32 [K=1024][N=256]
__device__ float  g_Wcat[KCAT*FEAT];                  // fp32 [K=1280][N=1024]; rows 0:256=E, 256:1280=G
__device__ float  g_CtS[256*FEAT];
__device__ float2 g_Abar[2*STATE];
__device__ float2 g_coef[2*STATE];
// fp16 activation / weight buffers
__device__ __half g_acat[(size_t)BS*1280];     // [row][1280] = [xs(256)|h(1024)]
__device__ __half g_h2  [(size_t)BS*1024];     // [row][1024]
__device__ __half g_hid [(size_t)BS*4096];     // [row][4096]
__device__ __half g_wp2 [256*1024];            // [N=256][K=1024]
__device__ __half g_wcat2[(size_t)1024*1280];  // [N=1024][K=1280]
__device__ __half g_w12 [(size_t)4096*1024];   // [N=4096][K=1024]
__device__ __half g_w22 [(size_t)1024*4096];   // [N=1024][K=4096]

// ---------------- helpers ----------------
__device__ __forceinline__ uint32_t smem_u32(const void* p){
    uint32_t a; asm("{ .reg .u64 t; cvta.to.shared.u64 t, %1; cvt.u32.u64 %0, t; }":"=r"(a):"l"(p)); return a;
}
__device__ __forceinline__ void cp16(uint32_t dst, const void* src){
    asm volatile("cp.async.cg.shared.global [%0], [%1], 16;"::"r"(dst),"l"(src):"memory");
}
#define SW128(o) ((o) ^ (((o)>>3)&0x70))

// ---------------- small setup kernels ----------------
__global__ void k_coef(const float* fLA, const float* fAi, const float* fdt,
                       const float* bLA, const float* bAi, const float* bdt) {
    int t = threadIdx.x;
    if (t >= 128) return;
    int d = t >> 6, n = t & 63;
    const float* LA  = d ? bLA : fLA;
    const float* Ai  = d ? bAi : fAi;
    const float* LDT = d ? bdt : fdt;
    float dt = expf(LDT[n]);
    float ar = -expf(LA[n]);
    float ai = Ai[n];
    float e  = expf(ar*dt);
    float Abr = e*cosf(ai*dt);
    float Abi = e*sinf(ai*dt);
    float dr = ar + 1e-8f, di = ai;
    float den = dr*dr + di*di;
    float nr = Abr - 1.0f, ni = Abi;
    g_Abar[t] = make_float2(Abr, Abi);
    g_coef[t] = make_float2((nr*dr + ni*di)/den, (ni*dr - nr*di)/den);
}

__global__ void k_silu(const float* __restrict__ cond) {
    int i = blockIdx.x*256 + threadIdx.x;
    if (i < B_SZ*FEAT) { float c = cond[i]; g_silu[i] = c / (1.0f + expf(-c)); }
}

// batch-split ada: grid (C6F/256, B_SZ)
__global__ void k_ada(const float* __restrict__ W, const float* __restrict__ bias) {
    __shared__ float sc[FEAT];
    int b = blockIdx.y;
    int tid = threadIdx.x;
    for (int i = tid; i < FEAT; i += 256) sc[i] = g_silu[b*FEAT + i];
    __syncthreads();
    int col = blockIdx.x*256 + tid;
    float a = 0.f;
    for (int k = 0; k < FEAT; k++) a += sc[k]*W[k*C6F + col];
    g_ada[b*C6F + col] = a + bias[col];
}

__global__ void k_wp(const float* fBr, const float* fBi, const float* bBr, const float* bBi) {
    int idx = blockIdx.x*256 + threadIdx.x;   // FEAT*256
    int c = idx & 255, f = idx >> 8;
    int d = c >> 7, p = (c >> 6) & 1, n = c & 63;
    float2 co = g_coef[d*64 + n];
    const float* Br = d ? bBr : fBr;
    const float* Bi = d ? bBi : fBi;
    float br = Br[n*FEAT + f], bi = Bi[n*FEAT + f];
    g_Wp[idx] = p ? (co.x*bi + co.y*br) : (co.x*br - co.y*bi);
}

__global__ void k_cts(const float* fCr, const float* fCi, const float* bCr, const float* bCi) {
    int idx = blockIdx.x*256 + threadIdx.x;   // 256*FEAT
    int f = idx & (FEAT-1), c = idx >> 10;
    int d = c >> 7, p = (c >> 6) & 1, n = c & 63;
    const float* Cp = p ? (d ? bCi : fCi) : (d ? bCr : fCr);
    float v = Cp[f*STATE + n];
    g_CtS[idx] = p ? -v : v;
}

__global__ void k_G(const float* fD, const float* bD, const float* oW) {
    int idx = blockIdx.x*256 + threadIdx.x;   // FEAT*FEAT
    int fp = idx & (FEAT-1), f = idx >> 10;
    g_Wcat[(256+f)*FEAT + fp] = fD[f]*oW[f*FEAT + fp] + bD[f]*oW[(FEAT+f)*FEAT + fp];
}

// transpose fp32 [K][N] -> fp16 [N][K]
__global__ void k_tsplit(const float* __restrict__ W, __half* __restrict__ B2,
                         int K, int N) {
    __shared__ float sm[32][33];
    int k0 = blockIdx.x*32, n0 = blockIdx.y*32;
    int tx = threadIdx.x, ty = threadIdx.y;
    #pragma unroll
    for (int r = 0; r < 32; r += 8)
        sm[ty+r][tx] = W[(size_t)(k0+ty+r)*N + n0 + tx];
    __syncthreads();
    #pragma unroll
    for (int r = 0; r < 32; r += 8) {
        int n = n0 + ty + r, k = k0 + tx;
        B2[(size_t)n*K + k] = __float2half_rn(sm[tx][ty+r]);
    }
}

// planar xs (fp32 in g_bu) -> g_acat cols 0..255 (fp16).  grid (SEQ/32, 256/32, B_SZ)
__global__ void k_xpose() {
    __shared__ float sm[32][33];
    int s0 = blockIdx.x*32, c0 = blockIdx.y*32, b = blockIdx.z;
    int tx = threadIdx.x, ty = threadIdx.y;
    int d = c0 >> 7, p = (c0 >> 6) & 1, n0 = c0 & 63;
    const float* src = g_bu + (((size_t)(d*2+p)*B_SZ + b)*STATE + n0)*SEQ;
    #pragma unroll
    for (int r = 0; r < 32; r += 8)
        sm[ty+r][tx] = src[(size_t)(ty+r)*SEQ + s0 + tx];
    __syncthreads();
    __half* dst = g_acat + ((size_t)(b*SEQ + s0))*1280 + c0;
    #pragma unroll
    for (int r = 0; r < 32; r += 8)
        dst[(size_t)(ty+r)*1280 + tx] = __float2half_rn(sm[tx][ty+r]);
}

// ---------------- layernorm + adaln -> fp16 ----------------
__global__ void k_ln_b(const float* __restrict__ in,
                       __half* __restrict__ outp, int out_ld, int base,
                       int sh_off, int sc_off) {
    int row = blockIdx.x;
    int b = row >> 12;
    int tid = threadIdx.x;
    float4 v = *(const float4*)(in + (size_t)row*FEAT + tid*4);
    float s = v.x+v.y+v.z+v.w;
    float q = v.x*v.x + v.y*v.y + v.z*v.z + v.w*v.w;
    #pragma unroll
    for (int o = 16; o > 0; o >>= 1) {
        s += __shfl_down_sync(0xffffffffu, s, o);
        q += __shfl_down_sync(0xffffffffu, q, o);
    }
    __shared__ float ss[8], sq[8];
    __shared__ float mu_s, rs_s;
    int w = tid >> 5, ln = tid & 31;
    if (ln == 0) { ss[w] = s; sq[w] = q; }
    __syncthreads();
    if (tid == 0) {
        float S=0.f, Q=0.f;
        #pragma unroll
        for (int i = 0; i < 8; i++) { S += ss[i]; Q += sq[i]; }
        float mu  = S * (1.0f/FEAT);
        float var = Q * (1.0f/FEAT) - mu*mu;
        mu_s = mu; rs_s = rsqrtf(var + LN_EPS);
    }
    __syncthreads();
    float mu = mu_s, rs = rs_s;
    const float* ada = g_ada + b*C6F;
    int f = tid*4;
    float val[4] = {v.x, v.y, v.z, v.w};
    __half* o = outp + (size_t)row*out_ld + base + f;
    #pragma unroll
    for (int c = 0; c < 4; c++) {
        float hv = (val[c]-mu)*rs*(1.0f+ada[sc_off+f+c]) + ada[sh_off+f+c];
        o[c] = __float2half_rn(hv);
    }
}

// ---------------- SIMT 128x128x8 GEMM (setup-only: E = CtS @ oW, grid (8,2)) ----
__global__ void __launch_bounds__(256) gemm_simt(
    const float* __restrict__ A, int lda,
    const float* __restrict__ B0, const float* __restrict__ B1, int ldb,
    float* __restrict__ C, int ldc, int K)
{
    __shared__ float As[8][128];
    __shared__ float Bs[8][128];
    const float* Bm = blockIdx.y ? B1 : B0;
    int tid = threadIdx.x;
    int m0 = blockIdx.y * 128;
    int n0 = blockIdx.x * 128;
    int tx = tid & 15, ty = tid >> 4;
    float acc[8][8];
    #pragma unroll
    for (int i = 0; i < 8; i++)
        #pragma unroll
        for (int j = 0; j < 8; j++) acc[i][j] = 0.f;
    int aRow = tid >> 1;
    int aK   = (tid & 1) * 4;
    int bRow = tid >> 5;
    int bCol = (tid & 31) * 4;
    const float* Ap = A + (size_t)(m0 + aRow)*lda + aK;
    const float* Bp = Bm + (size_t)bRow*ldb + n0 + bCol;
    for (int k0 = 0; k0 < K; k0 += 8) {
        float4 av = *(const float4*)(Ap + k0);
        float4 bv = *(const float4*)(Bp + (size_t)k0*ldb);
        __syncthreads();
        As[aK+0][aRow]=av.x; As[aK+1][aRow]=av.y; As[aK+2][aRow]=av.z; As[aK+3][aRow]=av.w;
        *(float4*)(&Bs[bRow][bCol]) = bv;
        __syncthreads();
        #pragma unroll
        for (int kk = 0; kk < 8; kk++) {
            float af[8], bf[8];
            *(float4*)(af)   = *(const float4*)(&As[kk][ty*8]);
            *(float4*)(af+4) = *(const float4*)(&As[kk][ty*8+4]);
            *(float4*)(bf)   = *(const float4*)(&Bs[kk][tx*8]);
            *(float4*)(bf+4) = *(const float4*)(&Bs[kk][tx*8+4]);
            #pragma unroll
            for (int i = 0; i < 8; i++)
                #pragma unroll
                for (int j = 0; j < 8; j++)
                    acc[i][j] += af[i]*bf[j];
        }
    }
    #pragma unroll
    for (int i = 0; i < 8; i++) {
        int row = m0 + ty*8 + i;
        #pragma unroll
        for (int j4 = 0; j4 < 8; j4 += 4) {
            int col = n0 + tx*8 + j4;
            float4 o;
            o.x = acc[i][j4+0]; o.y = acc[i][j4+1]; o.z = acc[i][j4+2]; o.w = acc[i][j4+3];
            *(float4*)(C + (size_t)row*ldc + col) = o;
        }
    }
}

// ---------------- parallel S5 scan: smem-staged coalesced I/O, in-place in g_bu --
__global__ void __launch_bounds__(128) k_scan() {
    __shared__ float sbr[SEQ], sbi[SEQ];
    __shared__ float sr[128], si[128];
    int bid = blockIdx.x;
    int d   = bid >> 8;
    int rem = bid & 255;
    int b = rem >> 6, n = rem & 63;
    int tid = threadIdx.x;
    float2 A = g_Abar[d*64 + n];
    float* bur = g_bu + ((size_t)((d*2+0)*B_SZ + b)*STATE + n)*SEQ;
    float* bui = g_bu + ((size_t)((d*2+1)*B_SZ + b)*STATE + n)*SEQ;

    // coalesced load (with direction flip into logical order)
    for (int i = tid; i < SEQ; i += 128) {
        int s = d ? (SEQ-1-i) : i;
        sbr[i] = bur[s]; sbi[i] = bui[s];
    }
    __syncthreads();

    float xr[32], xi[32];
    float cr = 0.f, ci = 0.f;
    #pragma unroll
    for (int j = 0; j < 32; j++) {
        int i = tid*32 + j;
        float ur = sbr[i], ui = sbi[i];
        float nr = A.x*cr - A.y*ci + ur;
        float ni = A.x*ci + A.y*cr + ui;
        cr = nr; ci = ni; xr[j] = cr; xi[j] = ci;
    }
    sr[tid] = cr; si[tid] = ci;
    __syncthreads();
    float mr = A.x, mi = A.y;
    #pragma unroll
    for (int e = 0; e < 5; e++) { float t = mr*mr - mi*mi; mi = 2.f*mr*mi; mr = t; }
    for (int off = 1; off < 128; off <<= 1) {
        float c0 = sr[tid], c1 = si[tid];
        float p0 = 0.f, p1 = 0.f;
        if (tid >= off) { p0 = sr[tid-off]; p1 = si[tid-off]; }
        __syncthreads();
        sr[tid] = c0 + mr*p0 - mi*p1;
        si[tid] = c1 + mr*p1 + mi*p0;
        __syncthreads();
        float t = mr*mr - mi*mi; mi = 2.f*mr*mi; mr = t;
    }
    float pr = 0.f, pi = 0.f;
    if (tid > 0) { pr = sr[tid-1]; pi = si[tid-1]; }

    #pragma unroll
    for (int j = 0; j < 32; j++) {
        float t0 = A.x*pr - A.y*pi;
        float t1 = A.x*pi + A.y*pr;
        pr = t0; pi = t1;
        int i = tid*32 + j;
        sbr[i] = xr[j] + pr;
        sbi[i] = xi[j] + pi;
    }
    __syncthreads();
    // coalesced writeback (in-place; un-flip)
    for (int i = tid; i < SEQ; i += 128) {
        int s = d ? (SEQ-1-i) : i;
        bur[s] = sbr[i]; bui[s] = sbi[i];
    }
}

// ---------------- HMMA fp16 GEMM: 128x128 tile, 3-stage cp.async pipeline -------
constexpr int EPI_BU   = 1;   // planar bu store (fp32, coalesced via smem transpose)
constexpr int EPI_MAIN = 2;   // Cf = aux1 + gate*(acc+bias)
constexpr int EPI_GELU = 3;   // Ch fp16 = gelu(acc+bias)
constexpr int EPI_OUT  = 4;   // Cf = aux1 + gate*(acc+bias)

// smem: 3 stages x (A 128x64 fp16 = 16KB | B 128x64 fp16 = 16KB) = 96KB
#define TG_SMEM 98304

template<int EPI>
__global__ void __launch_bounds__(256)
tgemm(const __half* __restrict__ A2, int lda, int a0, int Ksec,
      const __half* __restrict__ Bm,
      float* __restrict__ Cf, __half* __restrict__ Ch,
      const float* __restrict__ bias,
      const float* __restrict__ aux1, const float* __restrict__ aux2)
{
    extern __shared__ __align__(1024) char smem[];
    const uint32_t sb = smem_u32(smem);
    const int tid = threadIdx.x, wid = tid >> 5, lane = tid & 31;
    const int m0 = blockIdx.y * 128, n0 = blockIdx.x * 128;
    const int wm = wid >> 2, wn = wid & 3;       // 2 x 4 warp grid; warp tile 64x32
    const int Ptot = Ksec >> 6;

    float acc[16][4];
    #pragma unroll
    for (int i = 0; i < 16; i++)
        #pragma unroll
        for (int j = 0; j < 4; j++) acc[i][j] = 0.f;

    // loader mapping: 256 thr; each loads 4x16B for A and 4x16B for B
    const int ar = tid >> 1, ac0 = (tid & 1)*4;
    const char* Abase = (const char*)(A2 + (size_t)(m0 + ar)*lda + a0);
    const char* Bbase = (const char*)(Bm + (size_t)(n0 + ar)*Ksec);

    auto stage_of = [&](int p){ int s = p % 3; return sb + (uint32_t)s*32768; };

    auto issue = [&](int p){
        uint32_t as_ = stage_of(p);
        uint32_t bs_ = as_ + 16384;
        const char* Asrc = Abase + (size_t)(p*64 + ac0*8)*2;
        const char* Bsrc = Bbase + (size_t)(p*64 + ac0*8)*2;
        #pragma unroll
        for (int i = 0; i < 4; i++) {
            uint32_t off = ar*128 + (ac0+i)*16;
            uint32_t sw = SW128(off);
            cp16(as_ + sw, Asrc + i*16);
            cp16(bs_ + sw, Bsrc + i*16);
        }
        asm volatile("cp.async.commit_group;" ::: "memory");
    };

    issue(0);
    if (Ptot > 1) issue(1);
    #pragma unroll 1
    for (int p = 0; p < Ptot; p++) {
        if (p + 2 < Ptot) {
            issue(p+2);
            asm volatile("cp.async.wait_group 2;" ::: "memory");
        } else if (p + 1 < Ptot) {
            asm volatile("cp.async.wait_group 1;" ::: "memory");
        } else {
            asm volatile("cp.async.wait_group 0;" ::: "memory");
        }
        __syncthreads();
        uint32_t as_ = stage_of(p);
        uint32_t bs_ = as_ + 16384;
        #pragma unroll
        for (int ks = 0; ks < 4; ks++) {
            uint32_t Af[4][4], Bf[2][4];
            #pragma unroll
            for (int mi = 0; mi < 4; mi++) {
                uint32_t off = (uint32_t)(wm*64 + mi*16 + (lane & 15))*128
                             + ks*32 + (lane >> 4)*16;
                uint32_t ad = as_ + SW128(off);
                asm volatile("ldmatrix.sync.aligned.m8n8.x4.shared.b16 {%0,%1,%2,%3}, [%4];"
                    : "=r"(Af[mi][0]), "=r"(Af[mi][1]), "=r"(Af[mi][2]), "=r"(Af[mi][3])
                    : "r"(ad));
            }
            #pragma unroll
            for (int nh = 0; nh < 2; nh++) {
                int n = wn*32 + nh*16 + ((lane >> 4) & 1)*8 + (lane & 7);
                uint32_t off = (uint32_t)n*128 + ks*32 + ((lane >> 3) & 1)*16;
                uint32_t ad = bs_ + SW128(off);
                asm volatile("ldmatrix.sync.aligned.m8n8.x4.shared.b16 {%0,%1,%2,%3}, [%4];"
                    : "=r"(Bf[nh][0]), "=r"(Bf[nh][1]), "=r"(Bf[nh][2]), "=r"(Bf[nh][3])
                    : "r"(ad));
            }
            #pragma unroll
            for (int mi = 0; mi < 4; mi++)
                #pragma unroll
                for (int nj = 0; nj < 4; nj++) {
                    float* c = acc[mi*4 + nj];
                    uint32_t b0 = Bf[nj>>1][(nj&1)*2], b1 = Bf[nj>>1][(nj&1)*2+1];
                    asm volatile(
                        "mma.sync.aligned.m16n8k16.row.col.f32.f16.f16.f32 "
                        "{%0,%1,%2,%3}, {%4,%5,%6,%7}, {%8,%9}, {%0,%1,%2,%3};"
                        : "+f"(c[0]), "+f"(c[1]), "+f"(c[2]), "+f"(c[3])
                        : "r"(Af[mi][0]), "r"(Af[mi][1]), "r"(Af[mi][2]), "r"(Af[mi][3]),
                          "r"(b0), "r"(b1));
                }
        }
        __syncthreads();
    }

    if (EPI == EPI_BU) {
        // stage tile in smem [col][row] (pad 132 keeps 16B alignment), then
        // write contiguous 128-float runs along s — fully coalesced.
        float* sf = (float*)smem;
        #pragma unroll
        for (int mi = 0; mi < 4; mi++)
            #pragma unroll
            for (int nj = 0; nj < 4; nj++) {
                float* a = acc[mi*4 + nj];
                int rl = wm*64 + mi*16 + (lane >> 2);
                int cl = wn*32 + nj*8 + (lane & 3)*2;
                #pragma unroll
                for (int h = 0; h < 2; h++) {
                    sf[(cl  )*132 + rl + h*8] = a[h*2+0];
                    sf[(cl+1)*132 + rl + h*8] = a[h*2+1];
                }
            }
        __syncthreads();
        int bb = m0 >> 12, s0 = m0 & 4095;
        #pragma unroll
        for (int pass = 0; pass < 4; pass++) {
            int col = pass*32 + wid*4 + (lane >> 3);
            int i0  = (lane & 7)*16;
            int cp  = n0 + col;
            float* dst = Cf + (((size_t)(cp>>6)*B_SZ + bb)*STATE + (cp&63))*SEQ + s0 + i0;
            const float* src = sf + col*132 + i0;
            #pragma unroll
            for (int i = 0; i < 16; i += 4)
                *(float4*)(dst + i) = *(const float4*)(src + i);
        }
        return;
    }

    // ---- epilogue from fragments (non-BU) ----
    #pragma unroll
    for (int mi = 0; mi < 4; mi++) {
        #pragma unroll
        for (int nj = 0; nj < 4; nj++) {
            float* a = acc[mi*4 + nj];
            int r0 = m0 + wm*64 + mi*16 + (lane >> 2);
            int c  = n0 + wn*32 + nj*8 + (lane & 3)*2;
            #pragma unroll
            for (int h = 0; h < 2; h++) {
                int row = r0 + h*8;
                float v0 = a[h*2+0], v1 = a[h*2+1];
                if (EPI == EPI_GELU) {
                    float t0 = v0 + bias[c],   t1 = v1 + bias[c+1];
                    float u0 = 0.7978845608028654f*(t0 + 0.044715f*t0*t0*t0);
                    float u1 = 0.7978845608028654f*(t1 + 0.044715f*t1*t1*t1);
                    float g0 = 0.5f*t0*(1.0f + tanhf(u0));
                    float g1 = 0.5f*t1*(1.0f + tanhf(u1));
                    *(__half2*)(Ch + (size_t)row*HIDN + c) =
                        __half2{__float2half_rn(g0), __float2half_rn(g1)};
                } else {
                    int bb = row >> 12;
                    float g0 = aux2[bb*C6F + c], g1 = aux2[bb*C6F + c + 1];
                    float2 ax = *(const float2*)(aux1 + (size_t)row*FEAT + c);
                    float2 o;
                    o.x = ax.x + g0*(v0 + bias[c]);
                    o.y = ax.y + g1*(v1 + bias[c+1]);
                    *(float2*)(Cf + (size_t)row*FEAT + c) = o;
                }
            }
        }
    }
}

// ---------------- launch ----------------
extern "C" void kernel_launch(void* const* d_in, const int* in_sizes, int n_in,
                              void* d_out, int out_size) {
    const float* x    = (const float*)d_in[0];
    const float* cond = (const float*)d_in[1];
    const float* adaW = (const float*)d_in[2];
    const float* adab = (const float*)d_in[3];
    const float *fLA, *fAi, *fBr, *fBi, *fCr, *fCi, *fD, *fdt;
    const float *bLA, *bAi, *bBr, *bBi, *bCr, *bCi, *bD, *bdt;
    const float *oW, *ob, *W1, *b1, *W2, *b2;
    if (in_sizes[4] == STATE) {
        fLA=(const float*)d_in[4];  fAi=(const float*)d_in[5];
        fBr=(const float*)d_in[6];  fBi=(const float*)d_in[7];
        fCr=(const float*)d_in[8];  fCi=(const float*)d_in[9];
        fD =(const float*)d_in[10]; fdt=(const float*)d_in[11];
        bLA=(const float*)d_in[12]; bAi=(const float*)d_in[13];
        bBr=(const float*)d_in[14]; bBi=(const float*)d_in[15];
        bCr=(const float*)d_in[16]; bCi=(const float*)d_in[17];
        bD =(const float*)d_in[18]; bdt=(const float*)d_in[19];
        oW =(const float*)d_in[20]; ob =(const float*)d_in[21];
        W1 =(const float*)d_in[22]; b1 =(const float*)d_in[23];
        W2 =(const float*)d_in[24]; b2 =(const float*)d_in[25];
    } else {
        oW =(const float*)d_in[4];  ob =(const float*)d_in[5];
        W1 =(const float*)d_in[6];  b1 =(const float*)d_in[7];
        W2 =(const float*)d_in[8];  b2 =(const float*)d_in[9];
        fLA=(const float*)d_in[11]; fAi=(const float*)d_in[12];
        fBr=(const float*)d_in[13]; fBi=(const float*)d_in[14];
        fCr=(const float*)d_in[15]; fCi=(const float*)d_in[16];
        fD =(const float*)d_in[17]; fdt=(const float*)d_in[18];
        bLA=(const float*)d_in[19]; bAi=(const float*)d_in[20];
        bBr=(const float*)d_in[21]; bBi=(const float*)d_in[22];
        bCr=(const float*)d_in[23]; bCi=(const float*)d_in[24];
        bD =(const float*)d_in[25]; bdt=(const float*)d_in[26];
    }
    float* out = (float*)d_out;

    float *pXmid, *pBu, *pAda, *pWp, *pWcat, *pCtS;
    __half *pAcat, *pH2, *pHid, *pWp2, *pWcat2, *pW12, *pW22;
    cudaGetSymbolAddress((void**)&pXmid, g_xmid);
    cudaGetSymbolAddress((void**)&pBu,   g_bu);
    cudaGetSymbolAddress((void**)&pAda,  g_ada);
    cudaGetSymbolAddress((void**)&pWp,   g_Wp);
    cudaGetSymbolAddress((void**)&pWcat, g_Wcat);
    cudaGetSymbolAddress((void**)&pCtS,  g_CtS);
    cudaGetSymbolAddress((void**)&pAcat, g_acat);
    cudaGetSymbolAddress((void**)&pH2,   g_h2);
    cudaGetSymbolAddress((void**)&pHid,  g_hid);
    cudaGetSymbolAddress((void**)&pWp2,  g_wp2);
    cudaGetSymbolAddress((void**)&pWcat2,g_wcat2);
    cudaGetSymbolAddress((void**)&pW12,  g_w12);
    cudaGetSymbolAddress((void**)&pW22,  g_w22);

    cudaFuncSetAttribute(tgemm<EPI_BU>,   cudaFuncAttributeMaxDynamicSharedMemorySize, TG_SMEM);
    cudaFuncSetAttribute(tgemm<EPI_MAIN>, cudaFuncAttributeMaxDynamicSharedMemorySize, TG_SMEM);
    cudaFuncSetAttribute(tgemm<EPI_GELU>, cudaFuncAttributeMaxDynamicSharedMemorySize, TG_SMEM);
    cudaFuncSetAttribute(tgemm<EPI_OUT>,  cudaFuncAttributeMaxDynamicSharedMemorySize, TG_SMEM);

    // ---- setup / precompute (fp32) ----
    k_coef<<<1,128>>>(fLA, fAi, fdt, bLA, bAi, bdt);
    k_silu<<<(B_SZ*FEAT+255)/256,256>>>(cond);
    k_ada<<<dim3(C6F/256, B_SZ),256>>>(adaW, adab);
    k_wp<<<(FEAT*256)/256,256>>>(fBr, fBi, bBr, bBi);
    k_cts<<<(256*FEAT)/256,256>>>(fCr, fCi, bCr, bCi);
    k_G<<<(FEAT*FEAT)/256,256>>>(fD, bD, oW);
    // E = CtS @ out_W halves -> g_Wcat rows 0:256 (single grid(8,2) launch)
    gemm_simt<<<dim3(8,2),256>>>(pCtS, FEAT, oW, oW + FEAT*FEAT, FEAT,
                                 pWcat, FEAT, FEAT);
    // ---- weight transpose to fp16 [N][K] ----
    dim3 tb(32,8);
    k_tsplit<<<dim3(FEAT/32, 256/32), tb>>>(pWp,   pWp2,   FEAT, 256);
    k_tsplit<<<dim3(KCAT/32, FEAT/32), tb>>>(pWcat, pWcat2, KCAT, FEAT);
    k_tsplit<<<dim3(FEAT/32, HIDN/32), tb>>>(W1,    pW12,   FEAT, HIDN);
    k_tsplit<<<dim3(HIDN/32, FEAT/32), tb>>>(W2,    pW22,   HIDN, FEAT);

    // ---- main pipeline ----
    // LN1 -> h portion of Acat (cols 256:1280)
    k_ln_b<<<BS,256>>>(x, pAcat, 1280, 256, /*sh1*/0, /*sc1*/FEAT);
    // Bu = h @ Wp (coalesced planar store)
    tgemm<EPI_BU><<<dim3(2, BS/128), 256, TG_SMEM>>>(
        pAcat, 1280, 256, FEAT, pWp2,
        pBu, nullptr, nullptr, nullptr, nullptr);
    // scan in-place in g_bu, then transpose xs -> g_acat cols 0..255
    k_scan<<<512,128>>>();
    k_xpose<<<dim3(SEQ/32, 256/32, B_SZ), tb>>>();
    // xmid = x + g1*( [xs|h] @ Wcat + ob )
    tgemm<EPI_MAIN><<<dim3(FEAT/128, BS/128), 256, TG_SMEM>>>(
        pAcat, 1280, 0, KCAT, pWcat2,
        pXmid, nullptr, ob, x, pAda + 2*FEAT);
    // LN2 -> h2
    k_ln_b<<<BS,256>>>(pXmid, pH2, 1024, 0, /*sh2*/3*FEAT, /*sc2*/4*FEAT);
    // hid = gelu(h2 @ W1 + b1)
    tgemm<EPI_GELU><<<dim3(HIDN/128, BS/128), 256, TG_SMEM>>>(
        pH2, 1024, 0, FEAT, pW12,
        nullptr, pHid, b1, nullptr, nullptr);
    // out = xmid + g2*( hid @ W2 + b2 )
    tgemm<EPI_OUT><<<dim3(FEAT/128, BS/128), 256, TG_SMEM>>>(
        pHid, 4096, 0, HIDN, pW22,
        out, nullptr, b2, pXmid, pAda + 5*FEAT);
    (void)n_in; (void)out_size;
}